// round 11
// baseline (speedup 1.0000x reference)
#include <cuda_runtime.h>
#include <stddef.h>
#include <stdint.h>

// Problem constants (fixed shapes for this problem)
#define BB 2048      // batch
#define SS 128       // seq len
#define DD 1024      // model dim
#define EE 8         // num experts
#define HH 2048      // expert hidden (2*D)
#define NSTEPS 5
#define NCLS 10
#define LN_EPS 1e-5f

// ---------------- scratch (static device globals; no runtime allocation) ---------
__device__ float g_h[(size_t)BB * DD];       // current hidden state h  (8 MB)
__device__ float g_hidden[(size_t)BB * DD];  // router MLP hidden      (8 MB)
__device__ float g_z[(size_t)BB * HH];       // expert hidden          (16 MB)
__device__ float g_z2[(size_t)BB * DD];      // expert pre-LN output   (8 MB)
__device__ int   g_active[BB];
__device__ int   g_route[BB];                // chosen expert this step, or -1
__device__ int   g_cnt[EE];                  // per-expert routed count this step
__device__ int   g_list[EE * BB];            // per-expert sample index lists

// ---------------- tf32 helpers ----------------------------------------------------
__device__ __forceinline__ uint32_t f2tf32(float x) {
    uint32_t y;
    asm("cvt.rna.tf32.f32 %0, %1;" : "=r"(y) : "f"(x));
    return y;
}
// x = hi + lo, both representable in tf32 (stored as float bit patterns)
__device__ __forceinline__ void split_tf32(float v, float& hi, float& lo) {
    const float hf = __uint_as_float(f2tf32(v));
    hi = hf;
    lo = __uint_as_float(f2tf32(v - hf));
}
__device__ __forceinline__ void mma8(float* c, const uint32_t* a, const uint32_t* b) {
    asm volatile(
        "mma.sync.aligned.m16n8k8.row.col.f32.tf32.tf32.f32 "
        "{%0,%1,%2,%3}, {%4,%5,%6,%7}, {%8,%9}, {%0,%1,%2,%3};"
        : "+f"(c[0]), "+f"(c[1]), "+f"(c[2]), "+f"(c[3])
        : "r"(a[0]), "r"(a[1]), "r"(a[2]), "r"(a[3]), "r"(b[0]), "r"(b[1]));
}

// ---------------- pooling: h[b,:] = mean over non-pad tokens of emb[ids] ---------
__global__ void k_pool(const int* __restrict__ ids, const float* __restrict__ emb) {
    const int b = blockIdx.x;
    const int t = threadIdx.x;          // 256 threads, each owns 4 consecutive dims
    float4 acc = make_float4(0.f, 0.f, 0.f, 0.f);
    int cnt = 0;
    const int* row = ids + (size_t)b * SS;
    for (int s = 0; s < SS; s++) {
        const int id = row[s];
        cnt += (id != 0);
        // emb row 0 (padding) is all zeros in the input, so unconditional add is exact
        const float4 v = *(const float4*)(emb + (size_t)id * DD + t * 4);
        acc.x += v.x; acc.y += v.y; acc.z += v.z; acc.w += v.w;
    }
    const float inv = 1.0f / (float)(cnt > 0 ? cnt : 1);
    float4 o = make_float4(acc.x * inv, acc.y * inv, acc.z * inv, acc.w * inv);
    *(float4*)(g_h + (size_t)b * DD + t * 4) = o;
    if (t == 0) g_active[b] = 1;
}

// ---------------- 3xTF32 tensor-core GEMM: C[M,N] = act(A[M,K] @ W[K,N] + bias) ---
// Block tile 128x64, BK=16, 128 threads = 4 warps laid out 2(M)x2(N), warp tile
// 64x32 via 4x4 m16n8k8 tf32 MMAs, 3 passes (hi*hi + hi*lo + lo*hi).
// Double-buffered SMEM (2 stages), one __syncthreads per panel:
//   prefetch gmem->regs (next) | MMA (current stage) | split+STS (other stage) | bar
// SMEM rows stride LD=20 floats: (20*g+tg) mod 32 hits all 32 banks -> all
// fragment loads conflict-free. Dynamic SMEM = 60 KB -> 3 CTAs/SM with
// __launch_bounds__(128,3) for latency hiding.
// GATHER: rows come from g_list[e]; grid.z = expert, early-exit past g_cnt[e].
template <bool GATHER, bool RELU, int N, int K>
__device__ __forceinline__ void gemm_tf32(const float* __restrict__ A,
                                          const float* __restrict__ W,
                                          const float* __restrict__ bias,
                                          float* __restrict__ Cout) {
    constexpr int BM = 128, BN = 64, BK = 16, LD = 20;
    extern __shared__ float sm[];
    float* Ah = sm;                      // [2][BM][LD]
    float* Al = Ah + 2 * BM * LD;        // [2][BM][LD]
    float* Wh = Al + 2 * BM * LD;        // [2][BN][LD]
    float* Wl = Wh + 2 * BN * LD;        // [2][BN][LD]

    const int e  = GATHER ? blockIdx.z : 0;
    const int m0 = blockIdx.y * BM;
    const int n0 = blockIdx.x * BN;

    int mcount = BB;
    const int* rl = nullptr;
    if (GATHER) {
        mcount = g_cnt[e];
        if (m0 >= mcount) return;
        rl = g_list + e * BB;
        W += (size_t)e * K * N;
        bias += (size_t)e * N;
    }

    const int tid = threadIdx.x;
    // A loader: rows ar, ar+32, ar+64, ar+96; cols ac..ac+3 (float4 gmem loads)
    const int ar = tid >> 2;             // 0..31
    const int ac = (tid & 3) * 4;
    const float* Ap[4];
#pragma unroll
    for (int i = 0; i < 4; i++) {
        const int mrow = m0 + ar + i * 32;
        int rr;
        if (GATHER) rr = (mrow < mcount) ? rl[mrow] : 0;   // safe dummy row 0
        else        rr = mrow;
        Ap[i] = A + (size_t)rr * K + ac;
    }
    // W loader: n = tid&63, k-block kq (8 consecutive k each)
    const int wn_l = tid & 63;
    const int kq   = tid >> 6;           // 0..1
    const float* Wp = W + (size_t)kq * 8 * N + n0 + wn_l;

    const int warp = tid >> 5;
    const int lane = tid & 31;
    const int wm = (warp & 1) * 64;      // warp M offset
    const int wn = (warp >> 1) * 32;     // warp N offset
    const int g  = lane >> 2;            // groupID 0..7
    const int tg = lane & 3;             // threadInGroup 0..3

    float acc[4][4][4];
#pragma unroll
    for (int mi = 0; mi < 4; mi++)
#pragma unroll
        for (int ni = 0; ni < 4; ni++)
#pragma unroll
            for (int q = 0; q < 4; q++) acc[mi][ni][q] = 0.f;

    float4 av[4];
    float  wv[8];

    // split + store a fetched panel into SMEM stage s
    auto store_stage = [&](int s) {
        float* Ad  = Ah + s * BM * LD;
        float* AdL = Al + s * BM * LD;
#pragma unroll
        for (int i = 0; i < 4; i++) {
            float h0, h1, h2, h3, l0, l1, l2, l3;
            split_tf32(av[i].x, h0, l0); split_tf32(av[i].y, h1, l1);
            split_tf32(av[i].z, h2, l2); split_tf32(av[i].w, h3, l3);
            const int r = ar + i * 32;
            *(float4*)&Ad[r * LD + ac]  = make_float4(h0, h1, h2, h3);
            *(float4*)&AdL[r * LD + ac] = make_float4(l0, l1, l2, l3);
        }
        float hw[8], lw[8];
#pragma unroll
        for (int i = 0; i < 8; i++) split_tf32(wv[i], hw[i], lw[i]);
        float* Wd  = Wh + s * BN * LD;
        float* WdL = Wl + s * BN * LD;
        *(float4*)&Wd[wn_l * LD + kq * 8]      = make_float4(hw[0], hw[1], hw[2], hw[3]);
        *(float4*)&Wd[wn_l * LD + kq * 8 + 4]  = make_float4(hw[4], hw[5], hw[6], hw[7]);
        *(float4*)&WdL[wn_l * LD + kq * 8]     = make_float4(lw[0], lw[1], lw[2], lw[3]);
        *(float4*)&WdL[wn_l * LD + kq * 8 + 4] = make_float4(lw[4], lw[5], lw[6], lw[7]);
    };

    // prologue: fetch panel 0, fill stage 0
#pragma unroll
    for (int i = 0; i < 4; i++) av[i] = *(const float4*)Ap[i];
#pragma unroll
    for (int i = 0; i < 8; i++) wv[i] = Wp[(size_t)i * N];
    store_stage(0);
    __syncthreads();

    for (int k0 = 0; k0 < K; k0 += BK) {
        const int st = (k0 >> 4) & 1;
        const bool nxt = (k0 + BK < K);
        if (nxt) {
#pragma unroll
            for (int i = 0; i < 4; i++) av[i] = *(const float4*)(Ap[i] + k0 + BK);
#pragma unroll
            for (int i = 0; i < 8; i++) wv[i] = Wp[(size_t)(k0 + BK + i) * N];
        }
        const float* Ahs = Ah + st * BM * LD;
        const float* Als = Al + st * BM * LD;
        const float* Whs = Wh + st * BN * LD;
        const float* Wls = Wl + st * BN * LD;
#pragma unroll
        for (int ks = 0; ks < BK; ks += 8) {
            uint32_t ah[4][4], alr[4][4], bh[4][2], bl[4][2];
#pragma unroll
            for (int mi = 0; mi < 4; mi++) {
                const int r = wm + mi * 16 + g;
                const float* p0 = Ahs + r * LD + ks + tg;
                ah[mi][0]  = __float_as_uint(p0[0]);
                ah[mi][1]  = __float_as_uint(p0[8 * LD]);
                ah[mi][2]  = __float_as_uint(p0[4]);
                ah[mi][3]  = __float_as_uint(p0[8 * LD + 4]);
                const float* p1 = Als + r * LD + ks + tg;
                alr[mi][0] = __float_as_uint(p1[0]);
                alr[mi][1] = __float_as_uint(p1[8 * LD]);
                alr[mi][2] = __float_as_uint(p1[4]);
                alr[mi][3] = __float_as_uint(p1[8 * LD + 4]);
            }
#pragma unroll
            for (int ni = 0; ni < 4; ni++) {
                const int c = wn + ni * 8 + g;
                const float* q0 = Whs + c * LD + ks + tg;
                bh[ni][0] = __float_as_uint(q0[0]);
                bh[ni][1] = __float_as_uint(q0[4]);
                const float* q1 = Wls + c * LD + ks + tg;
                bl[ni][0] = __float_as_uint(q1[0]);
                bl[ni][1] = __float_as_uint(q1[4]);
            }
#pragma unroll
            for (int mi = 0; mi < 4; mi++)
#pragma unroll
                for (int ni = 0; ni < 4; ni++) {
                    mma8(acc[mi][ni], ah[mi], bh[ni]);   // hi*hi
                    mma8(acc[mi][ni], ah[mi], bl[ni]);   // hi*lo
                    mma8(acc[mi][ni], alr[mi], bh[ni]);  // lo*hi
                }
        }
        if (nxt) store_stage(st ^ 1);
        __syncthreads();
    }

    // epilogue: C frag c0..c3 = rows (g, g+8), cols (tg*2, tg*2+1)
#pragma unroll
    for (int mi = 0; mi < 4; mi++) {
#pragma unroll
        for (int half = 0; half < 2; half++) {
            const int lr = wm + mi * 16 + g + half * 8;
            int gr;
            if (GATHER) {
                if (m0 + lr >= mcount) continue;
                gr = rl[m0 + lr];
            } else {
                gr = m0 + lr;
            }
#pragma unroll
            for (int ni = 0; ni < 4; ni++) {
                const int c = wn + ni * 8 + tg * 2;
                const float2 bv = *(const float2*)(bias + n0 + c);
                float v0 = acc[mi][ni][half * 2 + 0] + bv.x;
                float v1 = acc[mi][ni][half * 2 + 1] + bv.y;
                if (RELU) { v0 = fmaxf(v0, 0.f); v1 = fmaxf(v1, 0.f); }
                *(float2*)(Cout + (size_t)gr * N + n0 + c) = make_float2(v0, v1);
            }
        }
    }
}

#define GEMM_SMEM (((2 * 128 * 20) * 2 + (2 * 64 * 20) * 2) * (int)sizeof(float))

__global__ void __launch_bounds__(128, 3)
k_router1(const float* __restrict__ W, const float* __restrict__ bvec) {
    gemm_tf32<false, true, DD, DD>(g_h, W, bvec, g_hidden);
}
__global__ void __launch_bounds__(128, 3)
k_expert1(const float* __restrict__ W, const float* __restrict__ bvec) {
    gemm_tf32<true, true, HH, DD>(g_h, W, bvec, g_z);
}
__global__ void __launch_bounds__(128, 3)
k_expert2(const float* __restrict__ W, const float* __restrict__ bvec) {
    gemm_tf32<true, false, DD, HH>(g_z, W, bvec, g_z2);
}

// ---------------- reset per-step counters -----------------------------------------
__global__ void k_reset() {
    if (threadIdx.x < EE) g_cnt[threadIdx.x] = 0;
}

// ---------------- router head: logits (E+1) -> argmax -> routing bookkeeping ------
__global__ void k_router2(const float* __restrict__ W2, const float* __restrict__ b2) {
    const int b = blockIdx.x;
    const int tid = threadIdx.x;
    const float* hid = g_hidden + (size_t)b * DD;
    float acc[EE + 1];
#pragma unroll
    for (int j = 0; j <= EE; j++) acc[j] = 0.f;
    for (int k = tid; k < DD; k += 256) {
        const float hv = hid[k];
#pragma unroll
        for (int j = 0; j <= EE; j++) acc[j] += hv * W2[k * (EE + 1) + j];
    }
    __shared__ float red[EE + 1][272];
#pragma unroll
    for (int j = 0; j <= EE; j++) red[j][tid] = acc[j];
    __syncthreads();
    for (int off = 128; off > 0; off >>= 1) {
        if (tid < off) {
#pragma unroll
            for (int j = 0; j <= EE; j++) red[j][tid] += red[j][tid + off];
        }
        __syncthreads();
    }
    if (tid == 0) {
        float best = red[0][0] + b2[0];
        int act = 0;
#pragma unroll
        for (int j = 1; j <= EE; j++) {
            const float v = red[j][0] + b2[j];
            if (v > best) { best = v; act = j; }   // strict '>' == first-max (jnp.argmax)
        }
        const int a = g_active[b];
        int r = -1;
        if (a && act < EE) {
            r = act;
            const int p = atomicAdd(&g_cnt[act], 1);
            g_list[act * BB + p] = b;
        }
        g_route[b] = r;
        g_active[b] = (a && act < EE) ? 1 : 0;
    }
}

// ---------------- LayerNorm + residual:  h += LN(z2)*g + beta  (routed samples) ---
__global__ void k_ln(const float* __restrict__ eg, const float* __restrict__ ebt) {
    const int b = blockIdx.x;
    const int e = g_route[b];
    if (e < 0) return;
    const int tid = threadIdx.x;
    const float* z2 = g_z2 + (size_t)b * DD;
    float x[4];
#pragma unroll
    for (int i = 0; i < 4; i++) x[i] = z2[tid + i * 256];

    __shared__ float rb[256];
    rb[tid] = x[0] + x[1] + x[2] + x[3];
    __syncthreads();
    for (int off = 128; off > 0; off >>= 1) {
        if (tid < off) rb[tid] += rb[tid + off];
        __syncthreads();
    }
    const float mean = rb[0] * (1.0f / DD);
    __syncthreads();
    float vs = 0.f;
#pragma unroll
    for (int i = 0; i < 4; i++) { const float d = x[i] - mean; vs += d * d; }
    rb[tid] = vs;
    __syncthreads();
    for (int off = 128; off > 0; off >>= 1) {
        if (tid < off) rb[tid] += rb[tid + off];
        __syncthreads();
    }
    const float inv = rsqrtf(rb[0] * (1.0f / DD) + LN_EPS);
#pragma unroll
    for (int i = 0; i < 4; i++) {
        const int d = tid + i * 256;
        g_h[(size_t)b * DD + d] +=
            (x[i] - mean) * inv * eg[(size_t)e * DD + d] + ebt[(size_t)e * DD + d];
    }
}

// ---------------- output head: out[b,:] = h[b] @ o_W + o_b  (C=10) ----------------
__global__ void k_head(const float* __restrict__ oW, const float* __restrict__ ob,
                       float* __restrict__ out) {
    const int b = blockIdx.x;
    const int tid = threadIdx.x;
    const float* h = g_h + (size_t)b * DD;
    float acc[NCLS];
#pragma unroll
    for (int c = 0; c < NCLS; c++) acc[c] = 0.f;
    for (int k = tid; k < DD; k += 256) {
        const float hv = h[k];
#pragma unroll
        for (int c = 0; c < NCLS; c++) acc[c] += hv * oW[k * NCLS + c];
    }
    __shared__ float red[NCLS][272];
#pragma unroll
    for (int c = 0; c < NCLS; c++) red[c][tid] = acc[c];
    __syncthreads();
    for (int off = 128; off > 0; off >>= 1) {
        if (tid < off) {
#pragma unroll
            for (int c = 0; c < NCLS; c++) red[c][tid] += red[c][tid + off];
        }
        __syncthreads();
    }
    if (tid < NCLS) out[(size_t)b * NCLS + tid] = red[tid][0] + ob[tid];
}

// ---------------- launch sequence -------------------------------------------------
extern "C" void kernel_launch(void* const* d_in, const int* in_sizes, int n_in,
                              void* d_out, int out_size) {
    (void)in_sizes; (void)n_in; (void)out_size;
    const int*   ids = (const int*)d_in[0];
    const float* emb = (const float*)d_in[1];
    const float* rW1 = (const float*)d_in[2];
    const float* rb1 = (const float*)d_in[3];
    const float* rW2 = (const float*)d_in[4];
    const float* rb2 = (const float*)d_in[5];
    const float* eW1 = (const float*)d_in[6];
    const float* eb1 = (const float*)d_in[7];
    const float* eW2 = (const float*)d_in[8];
    const float* eb2 = (const float*)d_in[9];
    const float* eg  = (const float*)d_in[10];
    const float* ebt = (const float*)d_in[11];
    const float* oW  = (const float*)d_in[12];
    const float* ob  = (const float*)d_in[13];
    float* out = (float*)d_out;

    // 60 KB dynamic SMEM per GEMM CTA (idempotent host-side attribute set)
    cudaFuncSetAttribute(k_router1, cudaFuncAttributeMaxDynamicSharedMemorySize, GEMM_SMEM);
    cudaFuncSetAttribute(k_expert1, cudaFuncAttributeMaxDynamicSharedMemorySize, GEMM_SMEM);
    cudaFuncSetAttribute(k_expert2, cudaFuncAttributeMaxDynamicSharedMemorySize, GEMM_SMEM);

    k_pool<<<BB, 256>>>(ids, emb);
    for (int s = 0; s < NSTEPS; s++) {
        k_reset<<<1, 32>>>();
        k_router1<<<dim3(DD / 64, BB / 128, 1), 128, GEMM_SMEM>>>(rW1, rb1);
        k_router2<<<BB, 256>>>(rW2, rb2);
        k_expert1<<<dim3(HH / 64, BB / 128, EE), 128, GEMM_SMEM>>>(eW1, eb1);
        k_expert2<<<dim3(DD / 64, BB / 128, EE), 128, GEMM_SMEM>>>(eW2, eb2);
        k_ln<<<BB, 256>>>(eg, ebt);
    }
    k_head<<<BB, 256>>>(oW, ob, out);
}

// round 14
// speedup vs baseline: 1.0928x; 1.0928x over previous
#include <cuda_runtime.h>
#include <stddef.h>
#include <stdint.h>

// Problem constants (fixed shapes for this problem)
#define BB 2048      // batch
#define SS 128       // seq len
#define DD 1024      // model dim
#define EE 8         // num experts
#define HH 2048      // expert hidden (2*D)
#define NSTEPS 5
#define NCLS 10
#define LN_EPS 1e-5f

// ---------------- scratch (static device globals; no runtime allocation) ---------
__device__ float g_h[(size_t)BB * DD];       // current hidden state h  (8 MB)
__device__ float g_hidden[(size_t)BB * DD];  // router MLP hidden      (8 MB)
__device__ float g_z[(size_t)BB * HH];       // expert hidden          (16 MB)
__device__ float g_z2[(size_t)BB * DD];      // expert pre-LN output   (8 MB)
__device__ int   g_active[BB];
__device__ int   g_route[BB];                // chosen expert this step, or -1
__device__ int   g_cnt[EE];                  // per-expert routed count this step
__device__ int   g_list[EE * BB];            // per-expert sample index lists

// ---------------- tf32 helpers ----------------------------------------------------
__device__ __forceinline__ uint32_t f2tf32(float x) {
    uint32_t y;
    asm("cvt.rna.tf32.f32 %0, %1;" : "=r"(y) : "f"(x));
    return y;
}
// split raw float into (hi, lo) tf32 pair, as uint bit patterns for mma
__device__ __forceinline__ void split_u(float v, uint32_t& hi, uint32_t& lo) {
    hi = f2tf32(v);
    lo = f2tf32(v - __uint_as_float(hi));
}
__device__ __forceinline__ void mma8(float* c, const uint32_t* a, const uint32_t* b) {
    asm volatile(
        "mma.sync.aligned.m16n8k8.row.col.f32.tf32.tf32.f32 "
        "{%0,%1,%2,%3}, {%4,%5,%6,%7}, {%8,%9}, {%0,%1,%2,%3};"
        : "+f"(c[0]), "+f"(c[1]), "+f"(c[2]), "+f"(c[3])
        : "r"(a[0]), "r"(a[1]), "r"(a[2]), "r"(a[3]), "r"(b[0]), "r"(b[1]));
}

// ---------------- pooling: h[b,:] = mean over non-pad tokens of emb[ids] ---------
__global__ void k_pool(const int* __restrict__ ids, const float* __restrict__ emb) {
    const int b = blockIdx.x;
    const int t = threadIdx.x;          // 256 threads, each owns 4 consecutive dims
    float4 acc = make_float4(0.f, 0.f, 0.f, 0.f);
    int cnt = 0;
    const int* row = ids + (size_t)b * SS;
    for (int s = 0; s < SS; s++) {
        const int id = row[s];
        cnt += (id != 0);
        // emb row 0 (padding) is all zeros in the input, so unconditional add is exact
        const float4 v = *(const float4*)(emb + (size_t)id * DD + t * 4);
        acc.x += v.x; acc.y += v.y; acc.z += v.z; acc.w += v.w;
    }
    const float inv = 1.0f / (float)(cnt > 0 ? cnt : 1);
    float4 o = make_float4(acc.x * inv, acc.y * inv, acc.z * inv, acc.w * inv);
    *(float4*)(g_h + (size_t)b * DD + t * 4) = o;
    if (t == 0) g_active[b] = 1;
}

// ---------------- 3xTF32 tensor-core GEMM: C[M,N] = act(A[M,K] @ W[K,N] + bias) ---
// Block tile 128x64, BK=16, 256 threads = 8 warps laid out 4(M)x2(N), warp tile
// 32x32 via 2x4 m16n8k8 tf32 MMAs, 3 passes (hi*hi + hi*lo + lo*hi).
// SMEM holds the RAW fp32 panels (double-buffered, one __syncthreads per panel);
// the tf32 hi/lo split happens at fragment-load time (cvt+sub on the idle
// fma/alu pipes), halving SMEM loads AND stores vs storing hi/lo planes.
// SMEM rows stride LD=20 floats: (20*g + tg) mod 32 enumerates all 32 banks ->
// every fragment load is conflict-free. 30.7KB static smem, 2 CTAs/SM.
// Pipeline per panel: LDG prefetch (next) | MMA (stage s) | STS (stage s^1) | bar.
// GATHER: rows come from g_list[e]; grid.z = expert, early-exit past g_cnt[e].
template <bool GATHER, bool RELU, int N, int K>
__device__ __forceinline__ void gemm_tf32(const float* __restrict__ A,
                                          const float* __restrict__ W,
                                          const float* __restrict__ bias,
                                          float* __restrict__ Cout) {
    constexpr int BM = 128, BN = 64, BK = 16, LD = 20;
    __shared__ float As[2][BM][LD];
    __shared__ float Ws[2][BN][LD];

    const int e  = GATHER ? blockIdx.z : 0;
    const int m0 = blockIdx.y * BM;
    const int n0 = blockIdx.x * BN;

    int mcount = BB;
    const int* rl = nullptr;
    if (GATHER) {
        mcount = g_cnt[e];
        if (m0 >= mcount) return;
        rl = g_list + e * BB;
        W += (size_t)e * K * N;
        bias += (size_t)e * N;
    }

    const int tid = threadIdx.x;
    // A loader: rows ar, ar+64; cols ac..ac+3 (float4 gmem loads)
    const int ar = tid >> 2;             // 0..63
    const int ac = (tid & 3) * 4;
    int r0, r1;
    if (GATHER) {
        r0 = (m0 + ar      < mcount) ? rl[m0 + ar]      : 0;  // safe dummy row 0
        r1 = (m0 + ar + 64 < mcount) ? rl[m0 + ar + 64] : 0;  // (store is guarded)
    } else {
        r0 = m0 + ar; r1 = m0 + ar + 64;
    }
    const float* Ap0 = A + (size_t)r0 * K + ac;
    const float* Ap1 = A + (size_t)r1 * K + ac;
    // W loader: n = tid&63, k-quad kq*4.. (4 consecutive k per thread)
    const int wn_l = tid & 63;
    const int kq4  = (tid >> 6) * 4;     // 0,4,8,12
    const float* Wp = W + (size_t)kq4 * N + n0 + wn_l;

    const int warp = tid >> 5;
    const int lane = tid & 31;
    const int wm = (warp & 3) * 32;      // warp M offset
    const int wn = (warp >> 2) * 32;     // warp N offset
    const int g  = lane >> 2;            // groupID 0..7
    const int tg = lane & 3;             // threadInGroup 0..3

    float acc[2][4][4];
#pragma unroll
    for (int mi = 0; mi < 2; mi++)
#pragma unroll
        for (int ni = 0; ni < 4; ni++)
#pragma unroll
            for (int q = 0; q < 4; q++) acc[mi][ni][q] = 0.f;

    float4 a0v, a1v;
    float  wv[4];

    // prologue: fetch panel 0, store raw into stage 0
    a0v = *(const float4*)Ap0;
    a1v = *(const float4*)Ap1;
#pragma unroll
    for (int i = 0; i < 4; i++) wv[i] = Wp[(size_t)i * N];
    *(float4*)&As[0][ar][ac] = a0v;
    *(float4*)&As[0][ar + 64][ac] = a1v;
    *(float4*)&Ws[0][wn_l][kq4] = make_float4(wv[0], wv[1], wv[2], wv[3]);
    __syncthreads();

    for (int k0 = 0; k0 < K; k0 += BK) {
        const int st = (k0 >> 4) & 1;
        const bool nxt = (k0 + BK < K);
        if (nxt) {
            a0v = *(const float4*)(Ap0 + k0 + BK);
            a1v = *(const float4*)(Ap1 + k0 + BK);
#pragma unroll
            for (int i = 0; i < 4; i++) wv[i] = Wp[(size_t)(k0 + BK + i) * N];
        }
#pragma unroll
        for (int ks = 0; ks < BK; ks += 8) {
            uint32_t ah[2][4], alr[2][4], bh[4][2], bl[4][2];
#pragma unroll
            for (int mi = 0; mi < 2; mi++) {
                const int r = wm + mi * 16 + g;
                split_u(As[st][r][ks + tg],          ah[mi][0], alr[mi][0]);
                split_u(As[st][r + 8][ks + tg],      ah[mi][1], alr[mi][1]);
                split_u(As[st][r][ks + tg + 4],      ah[mi][2], alr[mi][2]);
                split_u(As[st][r + 8][ks + tg + 4],  ah[mi][3], alr[mi][3]);
            }
#pragma unroll
            for (int ni = 0; ni < 4; ni++) {
                const int c = wn + ni * 8 + g;
                split_u(Ws[st][c][ks + tg],      bh[ni][0], bl[ni][0]);
                split_u(Ws[st][c][ks + tg + 4],  bh[ni][1], bl[ni][1]);
            }
#pragma unroll
            for (int mi = 0; mi < 2; mi++)
#pragma unroll
                for (int ni = 0; ni < 4; ni++) {
                    mma8(acc[mi][ni], ah[mi], bh[ni]);   // hi*hi
                    mma8(acc[mi][ni], ah[mi], bl[ni]);   // hi*lo
                    mma8(acc[mi][ni], alr[mi], bh[ni]);  // lo*hi
                }
        }
        if (nxt) {
            const int ns = st ^ 1;
            *(float4*)&As[ns][ar][ac] = a0v;
            *(float4*)&As[ns][ar + 64][ac] = a1v;
            *(float4*)&Ws[ns][wn_l][kq4] = make_float4(wv[0], wv[1], wv[2], wv[3]);
        }
        __syncthreads();
    }

    // epilogue: C frag c0..c3 = rows (g, g+8), cols (tg*2, tg*2+1)
#pragma unroll
    for (int mi = 0; mi < 2; mi++) {
#pragma unroll
        for (int half = 0; half < 2; half++) {
            const int lr = wm + mi * 16 + g + half * 8;
            int gr;
            if (GATHER) {
                if (m0 + lr >= mcount) continue;
                gr = rl[m0 + lr];
            } else {
                gr = m0 + lr;
            }
#pragma unroll
            for (int ni = 0; ni < 4; ni++) {
                const int c = wn + ni * 8 + tg * 2;
                const float2 bv = *(const float2*)(bias + n0 + c);
                float v0 = acc[mi][ni][half * 2 + 0] + bv.x;
                float v1 = acc[mi][ni][half * 2 + 1] + bv.y;
                if (RELU) { v0 = fmaxf(v0, 0.f); v1 = fmaxf(v1, 0.f); }
                *(float2*)(Cout + (size_t)gr * N + n0 + c) = make_float2(v0, v1);
            }
        }
    }
}

__global__ void __launch_bounds__(256, 2)
k_router1(const float* __restrict__ W, const float* __restrict__ bvec) {
    gemm_tf32<false, true, DD, DD>(g_h, W, bvec, g_hidden);
}
__global__ void __launch_bounds__(256, 2)
k_expert1(const float* __restrict__ W, const float* __restrict__ bvec) {
    gemm_tf32<true, true, HH, DD>(g_h, W, bvec, g_z);
}
__global__ void __launch_bounds__(256, 2)
k_expert2(const float* __restrict__ W, const float* __restrict__ bvec) {
    gemm_tf32<true, false, DD, HH>(g_z, W, bvec, g_z2);
}

// ---------------- reset per-step counters -----------------------------------------
__global__ void k_reset() {
    if (threadIdx.x < EE) g_cnt[threadIdx.x] = 0;
}

// ---------------- router head: logits (E+1) -> argmax -> routing bookkeeping ------
__global__ void k_router2(const float* __restrict__ W2, const float* __restrict__ b2) {
    const int b = blockIdx.x;
    const int tid = threadIdx.x;
    const float* hid = g_hidden + (size_t)b * DD;
    float acc[EE + 1];
#pragma unroll
    for (int j = 0; j <= EE; j++) acc[j] = 0.f;
    for (int k = tid; k < DD; k += 256) {
        const float hv = hid[k];
#pragma unroll
        for (int j = 0; j <= EE; j++) acc[j] += hv * W2[k * (EE + 1) + j];
    }
    __shared__ float red[EE + 1][272];
#pragma unroll
    for (int j = 0; j <= EE; j++) red[j][tid] = acc[j];
    __syncthreads();
    for (int off = 128; off > 0; off >>= 1) {
        if (tid < off) {
#pragma unroll
            for (int j = 0; j <= EE; j++) red[j][tid] += red[j][tid + off];
        }
        __syncthreads();
    }
    if (tid == 0) {
        float best = red[0][0] + b2[0];
        int act = 0;
#pragma unroll
        for (int j = 1; j <= EE; j++) {
            const float v = red[j][0] + b2[j];
            if (v > best) { best = v; act = j; }   // strict '>' == first-max (jnp.argmax)
        }
        const int a = g_active[b];
        int r = -1;
        if (a && act < EE) {
            r = act;
            const int p = atomicAdd(&g_cnt[act], 1);
            g_list[act * BB + p] = b;
        }
        g_route[b] = r;
        g_active[b] = (a && act < EE) ? 1 : 0;
    }
}

// ---------------- LayerNorm + residual:  h += LN(z2)*g + beta  (routed samples) ---
__global__ void k_ln(const float* __restrict__ eg, const float* __restrict__ ebt) {
    const int b = blockIdx.x;
    const int e = g_route[b];
    if (e < 0) return;
    const int tid = threadIdx.x;
    const float* z2 = g_z2 + (size_t)b * DD;
    float x[4];
#pragma unroll
    for (int i = 0; i < 4; i++) x[i] = z2[tid + i * 256];

    __shared__ float rb[256];
    rb[tid] = x[0] + x[1] + x[2] + x[3];
    __syncthreads();
    for (int off = 128; off > 0; off >>= 1) {
        if (tid < off) rb[tid] += rb[tid + off];
        __syncthreads();
    }
    const float mean = rb[0] * (1.0f / DD);
    __syncthreads();
    float vs = 0.f;
#pragma unroll
    for (int i = 0; i < 4; i++) { const float d = x[i] - mean; vs += d * d; }
    rb[tid] = vs;
    __syncthreads();
    for (int off = 128; off > 0; off >>= 1) {
        if (tid < off) rb[tid] += rb[tid + off];
        __syncthreads();
    }
    const float inv = rsqrtf(rb[0] * (1.0f / DD) + LN_EPS);
#pragma unroll
    for (int i = 0; i < 4; i++) {
        const int d = tid + i * 256;
        g_h[(size_t)b * DD + d] +=
            (x[i] - mean) * inv * eg[(size_t)e * DD + d] + ebt[(size_t)e * DD + d];
    }
}

// ---------------- output head: out[b,:] = h[b] @ o_W + o_b  (C=10) ----------------
__global__ void k_head(const float* __restrict__ oW, const float* __restrict__ ob,
                       float* __restrict__ out) {
    const int b = blockIdx.x;
    const int tid = threadIdx.x;
    const float* h = g_h + (size_t)b * DD;
    float acc[NCLS];
#pragma unroll
    for (int c = 0; c < NCLS; c++) acc[c] = 0.f;
    for (int k = tid; k < DD; k += 256) {
        const float hv = h[k];
#pragma unroll
        for (int c = 0; c < NCLS; c++) acc[c] += hv * oW[k * NCLS + c];
    }
    __shared__ float red[NCLS][272];
#pragma unroll
    for (int c = 0; c < NCLS; c++) red[c][tid] = acc[c];
    __syncthreads();
    for (int off = 128; off > 0; off >>= 1) {
        if (tid < off) {
#pragma unroll
            for (int c = 0; c < NCLS; c++) red[c][tid] += red[c][tid + off];
        }
        __syncthreads();
    }
    if (tid < NCLS) out[(size_t)b * NCLS + tid] = red[tid][0] + ob[tid];
}

// ---------------- launch sequence -------------------------------------------------
extern "C" void kernel_launch(void* const* d_in, const int* in_sizes, int n_in,
                              void* d_out, int out_size) {
    (void)in_sizes; (void)n_in; (void)out_size;
    const int*   ids = (const int*)d_in[0];
    const float* emb = (const float*)d_in[1];
    const float* rW1 = (const float*)d_in[2];
    const float* rb1 = (const float*)d_in[3];
    const float* rW2 = (const float*)d_in[4];
    const float* rb2 = (const float*)d_in[5];
    const float* eW1 = (const float*)d_in[6];
    const float* eb1 = (const float*)d_in[7];
    const float* eW2 = (const float*)d_in[8];
    const float* eb2 = (const float*)d_in[9];
    const float* eg  = (const float*)d_in[10];
    const float* ebt = (const float*)d_in[11];
    const float* oW  = (const float*)d_in[12];
    const float* ob  = (const float*)d_in[13];
    float* out = (float*)d_out;

    k_pool<<<BB, 256>>>(ids, emb);
    for (int s = 0; s < NSTEPS; s++) {
        k_reset<<<1, 32>>>();
        k_router1<<<dim3(DD / 64, BB / 128, 1), 256>>>(rW1, rb1);
        k_router2<<<BB, 256>>>(rW2, rb2);
        k_expert1<<<dim3(HH / 64, BB / 128, EE), 256>>>(eW1, eb1);
        k_expert2<<<dim3(DD / 64, BB / 128, EE), 256>>>(eW2, eb2);
        k_ln<<<BB, 256>>>(eg, ebt);
    }
    k_head<<<BB, 256>>>(oW, ob, out);
}